// round 5
// baseline (speedup 1.0000x reference)
#include <cuda_runtime.h>
#include <cuda_bf16.h>

// SE3Transform (PARTIAL_DENSE): for m in [0,M), i in [0,N):
//   nb = batch[i] + m*B;  out_pos[m*N+i] = R[nb] @ xyz[i] + p[nb];  out_batch[m*N+i] = nb
// Inputs: trans [M*B,4,4] f32, xyz [N,3] f32, batch [N] i32.
// Output: new_pos.ravel() [M*N*3] f32 ++ new_batch [M*N] as f32.
//
// R4 findings: latency/occupancy-bound (no pipe >55%, occ 50.5%). 256-thr
// blocks at 42 regs -> only 6 CTA/SM + bad wave quantization (978 CTAs).
// R5: 128-thr blocks (12 CTA/SM residency, ~1954 CTAs -> tiny tail), pin
// regs with __launch_bounds__(128,12). Table stays float2-SoA (conflict-free),
// 4 slices amortized per thread.

#define BATCH_B 16
#define NMAT    128          // M*B
#define NPAIR   6            // float2 pairs per matrix (12 floats)
#define SL      4            // slices handled per thread

__global__ void __launch_bounds__(128, 12) se3_kernel(
        const float*  __restrict__ trans,
        const float4* __restrict__ xyz4,
        const float*  __restrict__ xyz,
        const int4*   __restrict__ batch4,
        const int*    __restrict__ batch,
        float* __restrict__ out,
        int N, int G, int M,
        long long posElems, int writeBatch)
{
    // float2-SoA transform table: s2[j*NMAT + mat] = (trans[mat][2j], trans[mat][2j+1])
    __shared__ float2 s2[NPAIR * NMAT];   // 6 KB

    for (int idx = threadIdx.x; idx < NPAIR * NMAT; idx += blockDim.x) {
        int j   = idx >> 7;          // idx / 128
        int mat = idx & 127;         // idx % 128
        const float2* src = (const float2*)(trans + mat * 16);
        s2[idx] = __ldg(&src[j]);
    }
    __syncthreads();

    const int m0 = blockIdx.y * SL;       // first slice for this block

    for (int g = blockIdx.x * blockDim.x + threadIdx.x; g < G;
         g += gridDim.x * blockDim.x)
    {
        const int i0 = g * 4;

        if (i0 + 3 < N) {
            // ---- load 4 points once (MLP=4 up front) ----
            float4 a = __ldg(&xyz4[g * 3 + 0]);
            float4 b = __ldg(&xyz4[g * 3 + 1]);
            float4 c = __ldg(&xyz4[g * 3 + 2]);
            int4  bt = __ldg(&batch4[g]);

            float x[4], y[4], z[4];
            x[0] = a.x; y[0] = a.y; z[0] = a.z;
            x[1] = a.w; y[1] = b.x; z[1] = b.y;
            x[2] = b.z; y[2] = b.w; z[2] = c.x;
            x[3] = c.y; y[3] = c.z; z[3] = c.w;

            int b0[4];
            b0[0] = bt.x; b0[1] = bt.y; b0[2] = bt.z; b0[3] = bt.w;

            #pragma unroll
            for (int s = 0; s < SL; s++) {
                int m = m0 + s;
                if (m >= M) break;
                int mB = m * BATCH_B;
                long long sliceBase = (long long)m * N;

                float o[12];
                #pragma unroll
                for (int k = 0; k < 4; k++) {
                    int nb = b0[k] + mB;
                    float2 p0 = s2[0 * NMAT + nb];  // r00 r01
                    float2 p1 = s2[1 * NMAT + nb];  // r02 tx
                    float2 p2 = s2[2 * NMAT + nb];  // r10 r11
                    float2 p3 = s2[3 * NMAT + nb];  // r12 ty
                    float2 p4 = s2[4 * NMAT + nb];  // r20 r21
                    float2 p5 = s2[5 * NMAT + nb];  // r22 tz
                    o[k*3+0] = fmaf(p0.x, x[k], fmaf(p0.y, y[k], fmaf(p1.x, z[k], p1.y)));
                    o[k*3+1] = fmaf(p2.x, x[k], fmaf(p2.y, y[k], fmaf(p3.x, z[k], p3.y)));
                    o[k*3+2] = fmaf(p4.x, x[k], fmaf(p4.y, y[k], fmaf(p5.x, z[k], p5.y)));
                }

                float4* outv = (float4*)(out + (sliceBase + i0) * 3);
                outv[0] = make_float4(o[0], o[1], o[2],  o[3]);
                outv[1] = make_float4(o[4], o[5], o[6],  o[7]);
                outv[2] = make_float4(o[8], o[9], o[10], o[11]);

                if (writeBatch) {
                    float4* bo = (float4*)(out + posElems + sliceBase + i0);
                    *bo = make_float4((float)(b0[0] + mB), (float)(b0[1] + mB),
                                      (float)(b0[2] + mB), (float)(b0[3] + mB));
                }
            }
        } else {
            // ---- scalar tail ----
            for (int i = i0; i < N; i++) {
                float px = xyz[i * 3 + 0];
                float py = xyz[i * 3 + 1];
                float pz = xyz[i * 3 + 2];
                int bi = __ldg(&batch[i]);
                for (int s = 0; s < SL; s++) {
                    int m = m0 + s;
                    if (m >= M) break;
                    int nb = bi + m * BATCH_B;
                    float2 p0 = s2[0 * NMAT + nb];
                    float2 p1 = s2[1 * NMAT + nb];
                    float2 p2 = s2[2 * NMAT + nb];
                    float2 p3 = s2[3 * NMAT + nb];
                    float2 p4 = s2[4 * NMAT + nb];
                    float2 p5 = s2[5 * NMAT + nb];
                    long long ob = ((long long)m * N + i) * 3;
                    out[ob + 0] = fmaf(p0.x, px, fmaf(p0.y, py, fmaf(p1.x, pz, p1.y)));
                    out[ob + 1] = fmaf(p2.x, px, fmaf(p2.y, py, fmaf(p3.x, pz, p3.y)));
                    out[ob + 2] = fmaf(p4.x, px, fmaf(p4.y, py, fmaf(p5.x, pz, p5.y)));
                    if (writeBatch)
                        out[posElems + (long long)m * N + i] = (float)nb;
                }
            }
        }
    }
}

extern "C" void kernel_launch(void* const* d_in, const int* in_sizes, int n_in,
                              void* d_out, int out_size) {
    const float* trans = (const float*)d_in[0];   // [M*B, 4, 4]
    const float* xyz   = (const float*)d_in[1];   // [N, 3]
    const int*   batch = (const int*)d_in[2];     // [N]

    int numMat = in_sizes[0] / 16;        // M*B (= 128)
    int M      = numMat / BATCH_B;        // 8
    int N      = in_sizes[2];             // 500000

    long long posElems = (long long)M * N * 3;
    int writeBatch = ((long long)out_size >= posElems + (long long)M * N) ? 1 : 0;

    int G = (N + 3) / 4;                  // 4-point groups
    int threads = 128;
    int blocksX = (G + threads - 1) / threads;
    if (blocksX > 65535) blocksX = 65535;
    int blocksY = (M + SL - 1) / SL;      // slice groups

    dim3 grid(blocksX, blocksY, 1);
    se3_kernel<<<grid, threads>>>(
        trans,
        (const float4*)xyz, xyz,
        (const int4*)batch, batch,
        (float*)d_out,
        N, G, M, posElems, writeBatch);
}